// round 1
// baseline (speedup 1.0000x reference)
#include <cuda_runtime.h>
#include <math.h>

#define B_ 8
#define N_ 4096
#define C_ 768
#define H_ 8
#define HD 96
#define M_ (B_*N_)        // 32768 rows
#define QKV_COLS (3*C_)   // 2304

// ---------------- scratch (device globals: allocation-free) ----------------
__device__ float g_qkv[(size_t)M_ * QKV_COLS];   // [M, 3C]  (302 MB)
__device__ float g_ctx[(size_t)M_ * C_];         // [M, C]   (100 MB)
__device__ float g_S[B_ * H_ * HD * HD];         // logits/attn [bh][d][e]
__device__ float g_rn[B_ * 2 * C_];              // 1/max(||col||,eps) for q,k cols

// ---------------- packed fp32x2 helpers (Blackwell FFMA2 path) -------------
typedef unsigned long long u64;
__device__ __forceinline__ u64 pack2(float lo, float hi) {
    u64 r; asm("mov.b64 %0, {%1,%2};" : "=l"(r) : "f"(lo), "f"(hi)); return r;
}
__device__ __forceinline__ void unpack2(u64 v, float& lo, float& hi) {
    asm("mov.b64 {%0,%1}, %2;" : "=f"(lo), "=f"(hi) : "l"(v));
}
__device__ __forceinline__ u64 ffma2(u64 a, u64 b, u64 c) {
    u64 d; asm("fma.rn.f32x2 %0, %1, %2, %3;" : "=l"(d) : "l"(a), "l"(b), "l"(c)); return d;
}

// ---------------- SGEMM: 128x128x16 tile, 8x8/thread, f32x2 inner ----------
// A_GLOBAL: A comes from g_ctx.  C_GLOBAL: C goes to g_qkv.
template<bool A_GLOBAL, bool C_GLOBAL>
__global__ void __launch_bounds__(256, 2)
sgemm_kernel(const float* __restrict__ Ap, const float* __restrict__ Bm,
             float* __restrict__ Cp, const float* __restrict__ bias,
             int M, int N, int K, int lda, int ldb, int ldc)
{
    const float* A = A_GLOBAL ? (const float*)g_ctx : Ap;
    float*       C = C_GLOBAL ? (float*)g_qkv : Cp;

    __shared__ float As[2][16][128];
    __shared__ float Bs[2][16][128];

    const int tid = threadIdx.x;
    const int tm = tid & 15, tn = tid >> 4;
    const int m0 = blockIdx.y * 128, n0 = blockIdx.x * 128;

    u64 acc[8][4];
#pragma unroll
    for (int i = 0; i < 8; i++)
#pragma unroll
        for (int j = 0; j < 4; j++) acc[i][j] = pack2(0.f, 0.f);

    float4 ra[2], rb[2];
    // prologue: tile 0
#pragma unroll
    for (int l = 0; l < 2; l++) {
        int fid = tid + l * 256;
        int ar = fid >> 2, ac = fid & 3;
        ra[l] = *(const float4*)(A + (size_t)(m0 + ar) * lda + ac * 4);
        int br = fid >> 5, bc = fid & 31;
        rb[l] = *(const float4*)(Bm + (size_t)br * ldb + n0 + bc * 4);
    }
#pragma unroll
    for (int l = 0; l < 2; l++) {
        int fid = tid + l * 256;
        int ar = fid >> 2, ac = fid & 3;
        As[0][ac * 4 + 0][ar] = ra[l].x; As[0][ac * 4 + 1][ar] = ra[l].y;
        As[0][ac * 4 + 2][ar] = ra[l].z; As[0][ac * 4 + 3][ar] = ra[l].w;
        int br = fid >> 5, bc = fid & 31;
        *(float4*)&Bs[0][br][bc * 4] = rb[l];
    }
    __syncthreads();

    const int KT = K >> 4;
    for (int kt = 0; kt < KT; ++kt) {
        const int s = kt & 1;
        if (kt + 1 < KT) {
            int k0 = (kt + 1) << 4;
#pragma unroll
            for (int l = 0; l < 2; l++) {
                int fid = tid + l * 256;
                int ar = fid >> 2, ac = fid & 3;
                ra[l] = *(const float4*)(A + (size_t)(m0 + ar) * lda + k0 + ac * 4);
                int br = fid >> 5, bc = fid & 31;
                rb[l] = *(const float4*)(Bm + (size_t)(k0 + br) * ldb + n0 + bc * 4);
            }
        }
#pragma unroll
        for (int k = 0; k < 16; k++) {
            float4 a0 = *(const float4*)&As[s][k][tm * 8];
            float4 a1 = *(const float4*)&As[s][k][tm * 8 + 4];
            u64 b0 = *(const u64*)&Bs[s][k][tn * 8 + 0];
            u64 b1 = *(const u64*)&Bs[s][k][tn * 8 + 2];
            u64 b2 = *(const u64*)&Bs[s][k][tn * 8 + 4];
            u64 b3 = *(const u64*)&Bs[s][k][tn * 8 + 6];
            float av[8] = {a0.x, a0.y, a0.z, a0.w, a1.x, a1.y, a1.z, a1.w};
#pragma unroll
            for (int i = 0; i < 8; i++) {
                u64 ad = pack2(av[i], av[i]);
                acc[i][0] = ffma2(ad, b0, acc[i][0]);
                acc[i][1] = ffma2(ad, b1, acc[i][1]);
                acc[i][2] = ffma2(ad, b2, acc[i][2]);
                acc[i][3] = ffma2(ad, b3, acc[i][3]);
            }
        }
        __syncthreads();
        if (kt + 1 < KT) {
            const int d = s ^ 1;
#pragma unroll
            for (int l = 0; l < 2; l++) {
                int fid = tid + l * 256;
                int ar = fid >> 2, ac = fid & 3;
                As[d][ac * 4 + 0][ar] = ra[l].x; As[d][ac * 4 + 1][ar] = ra[l].y;
                As[d][ac * 4 + 2][ar] = ra[l].z; As[d][ac * 4 + 3][ar] = ra[l].w;
                int br = fid >> 5, bc = fid & 31;
                *(float4*)&Bs[d][br][bc * 4] = rb[l];
            }
            __syncthreads();
        }
    }

    // epilogue
#pragma unroll
    for (int i = 0; i < 8; i++) {
        int row = m0 + tm * 8 + i;
        float* cp = C + (size_t)row * ldc + n0 + tn * 8;
#pragma unroll
        for (int jp = 0; jp < 4; jp++) {
            float lo, hi; unpack2(acc[i][jp], lo, hi);
            if (bias) {
                lo += bias[n0 + tn * 8 + jp * 2];
                hi += bias[n0 + tn * 8 + jp * 2 + 1];
            }
            *(float2*)(cp + jp * 2) = make_float2(lo, hi);
        }
    }
}

// ---------------- column L2-norm reciprocals over token dim N --------------
// rn[b*1536 + j] = 1/max(||qkv[b, :, j]||_2, eps)   for j in [0, 1536)
__global__ void colnorm_kernel()
{
    const int b = blockIdx.y;
    const int lane = threadIdx.x & 31;
    const int w = threadIdx.x >> 5;              // 8 warps
    const int j = blockIdx.x * 32 + lane;        // j < 1536
    const float* p = g_qkv + (size_t)b * N_ * QKV_COLS + j;

    float s0 = 0.f, s1 = 0.f, s2 = 0.f, s3 = 0.f;
    for (int n0 = w * 4; n0 < N_; n0 += 32) {
        float v0 = p[(size_t)(n0 + 0) * QKV_COLS];
        float v1 = p[(size_t)(n0 + 1) * QKV_COLS];
        float v2 = p[(size_t)(n0 + 2) * QKV_COLS];
        float v3 = p[(size_t)(n0 + 3) * QKV_COLS];
        s0 += v0 * v0; s1 += v1 * v1; s2 += v2 * v2; s3 += v3 * v3;
    }
    __shared__ float red[8][32];
    red[w][lane] = (s0 + s1) + (s2 + s3);
    __syncthreads();
    if (w == 0) {
        float t = 0.f;
#pragma unroll
        for (int r = 0; r < 8; r++) t += red[r][lane];
        g_rn[b * (2 * C_) + j] = 1.f / fmaxf(sqrtf(t), 1e-12f);
    }
}

__global__ void zeroS_kernel()
{
    int i = blockIdx.x * blockDim.x + threadIdx.x;
    if (i < B_ * H_ * HD * HD) g_S[i] = 0.f;
}

// ---------------- QK^T partial: per (b,h), split N into 8 chunks -----------
__global__ void __launch_bounds__(256)
attn_partial_kernel()
{
    const int bh = blockIdx.x, b = bh >> 3, h = bh & 7;
    const int chunk = blockIdx.y;            // 8 chunks of 512 tokens
    const int tid = threadIdx.x;
    const int te = tid & 15, td = tid >> 4;

    __shared__ float qs[32][96];
    __shared__ float ks[32][96];

    float acc[6][6];
#pragma unroll
    for (int i = 0; i < 6; i++)
#pragma unroll
        for (int j = 0; j < 6; j++) acc[i][j] = 0.f;

    const size_t base = ((size_t)(b * N_ + chunk * 512)) * QKV_COLS + h * HD;
    for (int t = 0; t < 16; t++) {           // 16 tiles of 32 tokens
#pragma unroll
        for (int l = 0; l < 3; l++) {
            int fid = tid + l * 256;         // 768 float4 per tensor
            int r = fid / 24, c = fid % 24;
            size_t off = base + (size_t)(t * 32 + r) * QKV_COLS + c * 4;
            *(float4*)&qs[r][c * 4] = *(const float4*)(g_qkv + off);
            *(float4*)&ks[r][c * 4] = *(const float4*)(g_qkv + off + C_);
        }
        __syncthreads();
#pragma unroll 4
        for (int r = 0; r < 32; r++) {
            float a[6], bb[6];
#pragma unroll
            for (int i = 0; i < 6; i++) a[i] = qs[r][td * 6 + i];
#pragma unroll
            for (int j = 0; j < 6; j++) bb[j] = ks[r][te * 6 + j];
#pragma unroll
            for (int i = 0; i < 6; i++)
#pragma unroll
                for (int j = 0; j < 6; j++) acc[i][j] = fmaf(a[i], bb[j], acc[i][j]);
        }
        __syncthreads();
    }
    float* Sp = g_S + (size_t)bh * HD * HD;
#pragma unroll
    for (int i = 0; i < 6; i++)
#pragma unroll
        for (int j = 0; j < 6; j++)
            atomicAdd(&Sp[(td * 6 + i) * HD + te * 6 + j], acc[i][j]);
}

// ---------------- scale by 1/(||q|| ||k||) * temperature, softmax ----------
__global__ void softmax_kernel(const float* __restrict__ temp)
{
    const int bh = blockIdx.x, b = bh >> 3, h = bh & 7;
    const int d = threadIdx.x;
    if (d >= HD) return;
    float* row = g_S + (size_t)bh * HD * HD + d * HD;
    const float rq = g_rn[b * (2 * C_) + h * HD + d] * temp[h];
    const float* rk = g_rn + b * (2 * C_) + C_ + h * HD;

    float vals[HD];
    float m = -1e30f;
    for (int e = 0; e < HD; e++) {
        float v = row[e] * rq * rk[e];
        vals[e] = v;
        if (v > m) m = v;
    }
    float ssum = 0.f;
    for (int e = 0; e < HD; e++) {
        float v = expf(vals[e] - m);
        vals[e] = v;
        ssum += v;
    }
    float inv = 1.f / ssum;
    for (int e = 0; e < HD; e++) row[e] = vals[e] * inv;
}

// ---------------- AV: per (b,h) per 128-token block -------------------------
__global__ void __launch_bounds__(256)
av_kernel()
{
    const int nb = blockIdx.x;               // 32 blocks of 128 tokens
    const int bh = blockIdx.y, b = bh >> 3, h = bh & 7;
    const int tid = threadIdx.x;
    const int tdd = tid & 15, tnn = tid >> 4;

    __shared__ float at[96][100];            // attn transposed: at[e][d]
    __shared__ float vs[16][132];            // vs[e][n]

    const float* Sp = g_S + (size_t)bh * HD * HD;
#pragma unroll
    for (int l = 0; l < 36; l++) {
        int idx = tid + l * 256;             // 9216 values
        int d = idx / 96, e = idx % 96;
        at[e][d] = Sp[idx];
    }

    float acc[8][6];
#pragma unroll
    for (int i = 0; i < 8; i++)
#pragma unroll
        for (int j = 0; j < 6; j++) acc[i][j] = 0.f;

    const size_t basev = ((size_t)(b * N_ + nb * 128)) * QKV_COLS + 2 * C_ + h * HD;
    for (int ec = 0; ec < 6; ec++) {         // e chunks of 16
        __syncthreads();                     // prev compute done / at ready
#pragma unroll
        for (int l = 0; l < 2; l++) {
            int fid = tid + l * 256;         // 512 float4 = 128 rows x 16 e
            int r = fid >> 2, c = fid & 3;
            float4 v = *(const float4*)(g_qkv + basev + (size_t)r * QKV_COLS + ec * 16 + c * 4);
            vs[c * 4 + 0][r] = v.x; vs[c * 4 + 1][r] = v.y;
            vs[c * 4 + 2][r] = v.z; vs[c * 4 + 3][r] = v.w;
        }
        __syncthreads();
#pragma unroll
        for (int e = 0; e < 16; e++) {
            float4 va = *(const float4*)&vs[e][tnn * 8];
            float4 vb = *(const float4*)&vs[e][tnn * 8 + 4];
            const float2* wp = (const float2*)&at[ec * 16 + e][tdd * 6];
            float2 w01 = wp[0], w23 = wp[1], w45 = wp[2];
            float a[8] = {va.x, va.y, va.z, va.w, vb.x, vb.y, vb.z, vb.w};
            float w[6] = {w01.x, w01.y, w23.x, w23.y, w45.x, w45.y};
#pragma unroll
            for (int i = 0; i < 8; i++)
#pragma unroll
                for (int j = 0; j < 6; j++) acc[i][j] = fmaf(a[i], w[j], acc[i][j]);
        }
    }

#pragma unroll
    for (int i = 0; i < 8; i++) {
        size_t row = (size_t)(b * N_ + nb * 128 + tnn * 8 + i);
        float* cp = g_ctx + row * C_ + h * HD + tdd * 6;
        *(float2*)(cp + 0) = make_float2(acc[i][0], acc[i][1]);
        *(float2*)(cp + 2) = make_float2(acc[i][2], acc[i][3]);
        *(float2*)(cp + 4) = make_float2(acc[i][4], acc[i][5]);
    }
}

// ---------------- launch ----------------------------------------------------
extern "C" void kernel_launch(void* const* d_in, const int* in_sizes, int n_in,
                              void* d_out, int out_size)
{
    const float* x     = (const float*)d_in[0];
    const float* Wqkv  = (const float*)d_in[1];
    const float* temp  = (const float*)d_in[2];
    const float* Wproj = (const float*)d_in[3];
    const float* bproj = (const float*)d_in[4];
    float* out = (float*)d_out;

    // 1) qkv = x @ Wqkv  -> g_qkv [M, 3C]
    sgemm_kernel<false, true><<<dim3(QKV_COLS / 128, M_ / 128), 256>>>(
        x, Wqkv, nullptr, nullptr, M_, QKV_COLS, C_, C_, QKV_COLS, QKV_COLS);

    // 2) per-(b,channel) reciprocal L2 norms of q and k columns
    colnorm_kernel<<<dim3((2 * C_) / 32, B_), 256>>>();

    // 3) zero logits, then QK^T partial sums (split over N chunks)
    zeroS_kernel<<<(B_ * H_ * HD * HD + 255) / 256, 256>>>();
    attn_partial_kernel<<<dim3(B_ * H_, 8), 256>>>();

    // 4) scale + softmax (in place in g_S)
    softmax_kernel<<<B_ * H_, 96>>>(temp);

    // 5) ctx[m, h*96+d] = sum_e attn[d,e] * v[m, h*96+e]
    av_kernel<<<dim3(32, B_ * H_), 256>>>();

    // 6) out = ctx @ Wproj + bproj
    sgemm_kernel<true, false><<<dim3(C_ / 128, M_ / 128), 256>>>(
        nullptr, Wproj, out, bproj, M_, C_, C_, C_, C_, C_);
}